// round 17
// baseline (speedup 1.0000x reference)
#include <cuda_runtime.h>
#include <stdint.h>
#include <math.h>

// =============================== constants ===============================
namespace {
constexpr int Bz = 8, S = 2048, Dh = 128;
constexpr int CH = 32, CR = S / CH;       // 32 split-K chunks of 64 rows
constexpr int PA = 272;                   // image pitch bytes (128 bf16 cols)
constexpr int T64 = 64 * PA;              // 17408 B (64-row image)
constexpr int T128 = 128 * PA;            // 34816 B (128-row image)
// ktv images: KH, KL, VH, VL (all 64-row)
constexpr int K_KH = 0, K_KL = T64, K_VH = 2 * T64, K_VL = 3 * T64;
constexpr int SMEM_KTV = 4 * T64;         // 69632 -> 2-3 CTAs/SM
// qm images: QH, QL (64-row), MH, ML (128-row)
constexpr int Q_QH = 0, Q_QL = T64, Q_MH = 2 * T64, Q_ML = 2 * T64 + T128;
constexpr int SMEM_QM = 2 * T64 + 2 * T128;   // 104448 -> 2 CTAs/SM
constexpr int NT = 256;                   // 8 warps
}

// =============================== scratch =================================
__device__ float    g_Mp[Bz * CH * 128 * 128];  // split-K fp32 partials (16 MB)
__device__ uint32_t g_Mh[Bz][8192];             // M hi, bf16x2 row-major [d][v]
__device__ uint32_t g_Ml[Bz][8192];             // M lo

// =============================== helpers =================================
__device__ __forceinline__ uint32_t smem_u32(const void* p) {
    uint32_t a;
    asm("{ .reg .u64 t; cvta.to.shared.u64 t, %1; cvt.u32.u64 %0, t; }"
        : "=r"(a) : "l"(p));
    return a;
}
__device__ __forceinline__ void cp16(uint32_t dst, const void* src) {
    asm volatile("cp.async.cg.shared.global [%0], [%1], 16;"
                 :: "r"(dst), "l"(src));
}
__device__ __forceinline__ void cp_commit() {
    asm volatile("cp.async.commit_group;");
}
template <int N>
__device__ __forceinline__ void cp_wait() {
    asm volatile("cp.async.wait_group %0;" :: "n"(N));
}
// pack: low half = lo operand, high half = hi operand
__device__ __forceinline__ uint32_t cvt2(float hi, float lo) {
    uint32_t r;
    asm("cvt.rn.bf16x2.f32 %0, %1, %2;" : "=r"(r) : "f"(hi), "f"(lo));
    return r;
}
__device__ __forceinline__ void ldsm4(uint32_t* r, uint32_t a) {
    asm volatile("ldmatrix.sync.aligned.m8n8.x4.shared.b16 {%0,%1,%2,%3}, [%4];"
        : "=r"(r[0]), "=r"(r[1]), "=r"(r[2]), "=r"(r[3]) : "r"(a));
}
__device__ __forceinline__ void ldsm4t(uint32_t* r, uint32_t a) {
    asm volatile("ldmatrix.sync.aligned.m8n8.x4.trans.shared.b16 {%0,%1,%2,%3}, [%4];"
        : "=r"(r[0]), "=r"(r[1]), "=r"(r[2]), "=r"(r[3]) : "r"(a));
}
__device__ __forceinline__ void mma_bf16(float* d, const uint32_t* a,
                                         const uint32_t* b) {
    asm volatile(
        "mma.sync.aligned.m16n8k16.row.col.f32.bf16.bf16.f32 "
        "{%0,%1,%2,%3}, {%4,%5,%6,%7}, {%8,%9}, {%0,%1,%2,%3};"
        : "+f"(d[0]), "+f"(d[1]), "+f"(d[2]), "+f"(d[3])
        : "r"(a[0]), "r"(a[1]), "r"(a[2]), "r"(a[3]), "r"(b[0]), "r"(b[1]));
}

// convert one float4 -> hi/lo bf16x2 pairs, store at (row, col4), pitch PA
__device__ __forceinline__ void cvt_store(float4 x, char* hi, char* lo,
                                          int row, int c4) {
    uint32_t h0 = cvt2(x.y, x.x), h1 = cvt2(x.w, x.z);
    float a0 = __uint_as_float(h0 << 16);
    float a1 = __uint_as_float(h0 & 0xFFFF0000u);
    float a2 = __uint_as_float(h1 << 16);
    float a3 = __uint_as_float(h1 & 0xFFFF0000u);
    uint32_t l0 = cvt2(x.y - a1, x.x - a0);
    uint32_t l1 = cvt2(x.w - a3, x.z - a2);
    *(uint2*)(hi + row * PA + c4 * 2) = make_uint2(h0, h1);
    *(uint2*)(lo + row * PA + c4 * 2) = make_uint2(l0, l1);
}

// ===== kernel 1: split-K partial of M = K^T V; chunk = 64 s-rows =====
// 8 warps, warp tile 32(m=d) x 64(n=v); k = 64 (4 k16 steps).
__global__ void __launch_bounds__(NT, 2)
ktv_kernel(const float* __restrict__ Kp, const float* __restrict__ Vp) {
    extern __shared__ char sm[];
    const uint32_t sb = smem_u32(sm);
    const int tid = threadIdx.x, lane = tid & 31, wid = tid >> 5;
    const int b = blockIdx.x >> 5, c = blockIdx.x & 31;

    // load K,V chunk (each 64x128 fp32 = 2048 float4), convert to images.
    // A = K^T stored [k=s][m=d] = natural chunk layout; B = V same.
    {
        const float4* Kb =
            (const float4*)(Kp + (size_t)(b * S + c * CR) * Dh);
        const float4* Vb =
            (const float4*)(Vp + (size_t)(b * S + c * CR) * Dh);
        float4 kf[8], vf[8];
#pragma unroll
        for (int t = 0; t < 8; ++t) kf[t] = Kb[t * NT + tid];
#pragma unroll
        for (int t = 0; t < 8; ++t) vf[t] = Vb[t * NT + tid];
#pragma unroll
        for (int t = 0; t < 8; ++t) {
            const int i = t * NT + tid;
            cvt_store(kf[t], sm + K_KH, sm + K_KL, i >> 5, (i & 31) * 4);
        }
#pragma unroll
        for (int t = 0; t < 8; ++t) {
            const int i = t * NT + tid;
            cvt_store(vf[t], sm + K_VH, sm + K_VL, i >> 5, (i & 31) * 4);
        }
    }
    __syncthreads();

    // fragment bases: A trans [k][m], B trans [k][n]
    const int m_base = (wid & 3) * 32, n_base = (wid >> 2) * 64;
    const uint32_t aA =
        sb + K_KH +
        (uint32_t)((((lane & 7) + ((lane >> 4) << 3)) * PA) +
                   (m_base + ((lane >> 3) & 1) * 8) * 2);
    const uint32_t bA =
        sb + K_VH +
        (uint32_t)((((lane & 7) + (((lane >> 3) & 1) << 3)) * PA) +
                   (n_base + ((lane >> 4) << 3)) * 2);

    float acc[2][8][4] = {};
#pragma unroll
    for (int ks = 0; ks < 4; ++ks) {
        const uint32_t kb = (uint32_t)(ks * 16 * PA);
        uint32_t ah[2][4], al[2][4];
        ldsm4t(ah[0], aA + kb);
        ldsm4t(ah[1], aA + kb + 32);
        ldsm4t(al[0], aA + kb + T64);
        ldsm4t(al[1], aA + kb + T64 + 32);
        uint32_t bh[16], bl[16];
#pragma unroll
        for (int i = 0; i < 4; ++i) {
            ldsm4t(&bh[4 * i], bA + kb + 32 * i);
            ldsm4t(&bl[4 * i], bA + kb + T64 + 32 * i);
        }
#pragma unroll
        for (int mt = 0; mt < 2; ++mt)
#pragma unroll
            for (int nj = 0; nj < 8; ++nj) {
                float* d = acc[mt][nj];
                mma_bf16(d, ah[mt], &bh[2 * nj]);
                mma_bf16(d, al[mt], &bh[2 * nj]);
                mma_bf16(d, ah[mt], &bl[2 * nj]);
            }
    }

    const int g = lane >> 2, t = lane & 3;
    float* outp = g_Mp + ((size_t)(b * CH + c)) * 16384;
#pragma unroll
    for (int mt = 0; mt < 2; ++mt)
#pragma unroll
        for (int nj = 0; nj < 8; ++nj) {
            const int row = m_base + mt * 16 + g;
            const int col = n_base + nj * 8 + 2 * t;
            *(float2*)&outp[row * 128 + col] =
                make_float2(acc[mt][nj][0], acc[mt][nj][1]);
            *(float2*)&outp[(row + 8) * 128 + col] =
                make_float2(acc[mt][nj][2], acc[mt][nj][3]);
        }
}

// ====== kernel 2: reduce 32 partials -> M, convert to bf16 hi/lo ======
__global__ void __launch_bounds__(256, 1) reduce_kernel() {
    const int b = blockIdx.x >> 4, seg = blockIdx.x & 15;
    const int tid = threadIdx.x;
    const int d = seg * 8 + (tid >> 5), v0 = (tid & 31) * 4;
    const float* base = g_Mp + (size_t)b * CH * 16384 + d * 128 + v0;
    float4 s = make_float4(0.f, 0.f, 0.f, 0.f);
#pragma unroll
    for (int c = 0; c < CH; ++c) {
        float4 p = *(const float4*)(base + (size_t)c * 16384);
        s.x += p.x; s.y += p.y; s.z += p.z; s.w += p.w;
    }
    uint32_t h0 = cvt2(s.y, s.x), h1 = cvt2(s.w, s.z);
    float a0 = __uint_as_float(h0 << 16), a1 = __uint_as_float(h0 & 0xFFFF0000u);
    float a2 = __uint_as_float(h1 << 16), a3 = __uint_as_float(h1 & 0xFFFF0000u);
    uint32_t l0 = cvt2(s.y - a1, s.x - a0), l1 = cvt2(s.w - a3, s.z - a2);
    const int w = d * 64 + v0 / 2;
    *(uint2*)&g_Mh[b][w] = make_uint2(h0, h1);
    *(uint2*)&g_Ml[b][w] = make_uint2(l0, l1);
}

// ===== kernel 3: O tile (64 q-rows x 128) = Q tile @ M (scaled) =====
// 8 warps, warp tile 32(m) x 32(n); k = 128 (8 k16 steps).
__global__ void __launch_bounds__(NT, 2)
qm_kernel(const float* __restrict__ Qp, const float* __restrict__ sfp,
          float* __restrict__ Op) {
    extern __shared__ char sm[];
    const uint32_t sb = smem_u32(sm);
    const int tid = threadIdx.x, lane = tid & 31, wid = tid >> 5;
    const int b = blockIdx.x >> 5, qt = blockIdx.x & 31;

    // M hi/lo -> pitched 128-row images via cp.async (one group)
#pragma unroll
    for (int t = 0; t < 16; ++t) {
        const int i = t * NT + tid;          // 0..4095
        const int img = i >> 11;             // 0: hi, 1: lo
        const int r = (i >> 4) & 127, chk = i & 15;
        const char* src =
            (img ? (const char*)g_Ml[b] : (const char*)g_Mh[b]) +
            (size_t)r * 256 + chk * 16;
        cp16(sb + (img ? Q_ML : Q_MH) + r * PA + chk * 16, src);
    }
    cp_commit();

    // Q tile (64x128 fp32) -> registers -> Qh/Ql images
    {
        const float4* Qb =
            (const float4*)(Qp + (size_t)(b * S + qt * 64) * Dh);
        float4 qf[8];
#pragma unroll
        for (int t = 0; t < 8; ++t) qf[t] = Qb[t * NT + tid];
#pragma unroll
        for (int t = 0; t < 8; ++t) {
            const int i = t * NT + tid;
            cvt_store(qf[t], sm + Q_QH, sm + Q_QL, i >> 5, (i & 31) * 4);
        }
    }
    cp_wait<0>();
    __syncthreads();

    // fragment bases: A non-trans [m][k] (rows < 64), B trans [k][n]
    const int m_base = (wid & 1) * 32, n_base = (wid >> 1) * 32;
    const uint32_t aA =
        sb + Q_QH +
        (uint32_t)(((m_base + (lane & 7) + (((lane >> 3) & 1) << 3)) * PA) +
                   ((lane >> 4) << 3) * 2);
    const uint32_t bA =
        sb + Q_MH +
        (uint32_t)((((lane & 7) + (((lane >> 3) & 1) << 3)) * PA) +
                   (n_base + ((lane >> 4) << 3)) * 2);

    float acc[2][4][4] = {};
#pragma unroll
    for (int ks = 0; ks < 8; ++ks) {
        uint32_t ah[2][4], al[2][4];
        const uint32_t ka = (uint32_t)(ks * 32);
        ldsm4(ah[0], aA + ka);
        ldsm4(ah[1], aA + ka + 16 * PA);
        ldsm4(al[0], aA + ka + T64);
        ldsm4(al[1], aA + ka + T64 + 16 * PA);
        const uint32_t kbB = (uint32_t)(ks * 16 * PA);
        uint32_t bh[8], bl[8];
        ldsm4t(&bh[0], bA + kbB);
        ldsm4t(&bh[4], bA + kbB + 32);
        ldsm4t(&bl[0], bA + kbB + T128);
        ldsm4t(&bl[4], bA + kbB + T128 + 32);
#pragma unroll
        for (int mt = 0; mt < 2; ++mt)
#pragma unroll
            for (int nj = 0; nj < 4; ++nj) {
                float* d = acc[mt][nj];
                mma_bf16(d, ah[mt], &bh[2 * nj]);
                mma_bf16(d, al[mt], &bh[2 * nj]);
                mma_bf16(d, ah[mt], &bl[2 * nj]);
            }
    }

    const float inv = 1.0f / (sqrtf(128.0f) * sfp[0]);
    const int g = lane >> 2, t = lane & 3;
    float* outp = Op + (size_t)(b * S + qt * 64) * 128;
#pragma unroll
    for (int mt = 0; mt < 2; ++mt)
#pragma unroll
        for (int nj = 0; nj < 4; ++nj) {
            const int row = m_base + mt * 16 + g;
            const int col = n_base + nj * 8 + 2 * t;
            *(float2*)&outp[row * 128 + col] =
                make_float2(acc[mt][nj][0] * inv, acc[mt][nj][1] * inv);
            *(float2*)&outp[(row + 8) * 128 + col] =
                make_float2(acc[mt][nj][2] * inv, acc[mt][nj][3] * inv);
        }
}

// =============================== launch ===============================
extern "C" void kernel_launch(void* const* d_in, const int* in_sizes, int n_in,
                              void* d_out, int out_size) {
    // metadata order: qk (unused), qk_scaling_factor, query, key, value
    const float* sf = (const float*)d_in[1];
    const float* Q  = (const float*)d_in[2];
    const float* K  = (const float*)d_in[3];
    const float* V  = (const float*)d_in[4];
    float* O        = (float*)d_out;

    cudaFuncSetAttribute(ktv_kernel,
                         cudaFuncAttributeMaxDynamicSharedMemorySize, SMEM_KTV);
    cudaFuncSetAttribute(qm_kernel,
                         cudaFuncAttributeMaxDynamicSharedMemorySize, SMEM_QM);

    ktv_kernel<<<Bz * CH, NT, SMEM_KTV>>>(K, V);
    reduce_kernel<<<Bz * 16, 256>>>();
    qm_kernel<<<Bz * 32, NT, SMEM_QM>>>(Q, sf, O);
}